// round 7
// baseline (speedup 1.0000x reference)
#include <cuda_runtime.h>
#include <cuda_bf16.h>

namespace {

constexpr int Bn  = 512;
constexpr int DKn = 256;
constexpr int DVn = 256;
constexpr int Pn  = 2048;
constexpr float SCALEf = 1.0f / 16.0f;   // 1/sqrt(256)

constexpr int HALF_P = Pn / 2;           // 1024 p per K1 CTA
constexpr int HALF_V = DVn / 2;          // 128 out rows per K2 CTA

} // namespace

// scratch: masked/scaled energies (4 MB total -> L2-resident across the boundary)
__device__ float g_W[(size_t)Bn * Pn];

namespace {

// ---------------- K1: g_W[b,p] = mask ? SCALE * sum_d Q[b,d]*K[b,d,p] : 0 ----------------
__global__ void __launch_bounds__(256, 2)
energy_kernel(const float* __restrict__ Q,
              const float* __restrict__ K,
              const int*   __restrict__ mask)
{
    __shared__ float sQ[DKn];
    const int b    = blockIdx.x >> 1;
    const int half = blockIdx.x & 1;
    const int t    = threadIdx.x;

    sQ[t] = Q[(size_t)b * DKn + t];
    __syncthreads();

    const int p = half * HALF_P + 4 * t;
    const float* __restrict__ Kb = K + (size_t)b * DKn * Pn + p;

    float4 acc = make_float4(0.f, 0.f, 0.f, 0.f);

    #pragma unroll 1
    for (int d0 = 0; d0 < DKn; d0 += 16) {
        float4 kv[16];
        #pragma unroll
        for (int i = 0; i < 16; ++i)
            kv[i] = *reinterpret_cast<const float4*>(Kb + (size_t)(d0 + i) * Pn);
        #pragma unroll
        for (int i = 0; i < 16; ++i) {
            const float q = sQ[d0 + i];
            acc.x = fmaf(q, kv[i].x, acc.x);
            acc.y = fmaf(q, kv[i].y, acc.y);
            acc.z = fmaf(q, kv[i].z, acc.z);
            acc.w = fmaf(q, kv[i].w, acc.w);
        }
    }

    const int4 m = *reinterpret_cast<const int4*>(mask + (size_t)b * Pn + p);
    float4 e;
    e.x = m.x ? acc.x * SCALEf : 0.f;
    e.y = m.y ? acc.y * SCALEf : 0.f;
    e.z = m.z ? acc.z * SCALEf : 0.f;
    e.w = m.w ? acc.w * SCALEf : 0.f;
    *reinterpret_cast<float4*>(&g_W[(size_t)b * Pn + p]) = e;
}

// ---------------- K2: redundant row-softmax (L2-hot) + PV over a DV-half ----------------
__global__ void __launch_bounds__(256, 2)
softmax_pv_kernel(const float* __restrict__ V,
                  float*       __restrict__ out)
{
    __shared__ float sW[Pn];
    __shared__ float sRed[8];

    const int b    = blockIdx.x >> 1;
    const int half = blockIdx.x & 1;
    const int t    = threadIdx.x;
    const int lane = t & 31;
    const int warp = t >> 5;

    // ---- load full energy row (8 KB, L2-hot) ----
    const float* __restrict__ W = g_W + (size_t)b * Pn;
    const int pA = 4 * t;
    const int pB = (Pn / 2) + 4 * t;
    const float4 eA = *reinterpret_cast<const float4*>(W + pA);
    const float4 eB = *reinterpret_cast<const float4*>(W + pB);
    float e[8] = {eA.x, eA.y, eA.z, eA.w, eB.x, eB.y, eB.z, eB.w};

    // ---- block softmax over 2048 ----
    float lmax = e[0];
    #pragma unroll
    for (int i = 1; i < 8; ++i) lmax = fmaxf(lmax, e[i]);
    float v = lmax;
    #pragma unroll
    for (int o = 16; o; o >>= 1) v = fmaxf(v, __shfl_xor_sync(0xffffffffu, v, o));
    if (lane == 0) sRed[warp] = v;
    __syncthreads();
    float gmax = sRed[0];
    #pragma unroll
    for (int i = 1; i < 8; ++i) gmax = fmaxf(gmax, sRed[i]);
    __syncthreads();

    float w[8];
    float lsum = 0.f;
    #pragma unroll
    for (int i = 0; i < 8; ++i) {
        w[i] = __expf(e[i] - gmax);
        lsum += w[i];
    }
    v = lsum;
    #pragma unroll
    for (int o = 16; o; o >>= 1) v += __shfl_xor_sync(0xffffffffu, v, o);
    if (lane == 0) sRed[warp] = v;
    __syncthreads();
    float gsum = sRed[0];
    #pragma unroll
    for (int i = 1; i < 8; ++i) gsum += sRed[i];
    const float inv = 1.0f / gsum;

    // normalized weights into smem
    *reinterpret_cast<float4*>(&sW[pA]) =
        make_float4(w[0] * inv, w[1] * inv, w[2] * inv, w[3] * inv);
    *reinterpret_cast<float4*>(&sW[pB]) =
        make_float4(w[4] * inv, w[5] * inv, w[6] * inv, w[7] * inv);
    __syncthreads();

    // ---- PV: this CTA's 128 output rows over full P; 16 rows per warp ----
    const float* __restrict__ Vb = V + (size_t)b * DVn * Pn;
    const int vr0 = half * HALF_V + warp * (HALF_V / 8);

    #pragma unroll 1
    for (int r = 0; r < HALF_V / 8; ++r) {
        const float* __restrict__ Vr = Vb + (size_t)(vr0 + r) * Pn + lane * 4;
        float4 a4 = make_float4(0.f, 0.f, 0.f, 0.f);
        #pragma unroll
        for (int i = 0; i < Pn / 128; ++i) {       // 16 float4 loads in flight
            const float4 vv = *reinterpret_cast<const float4*>(Vr + i * 128);
            const float4 ww = *reinterpret_cast<const float4*>(&sW[i * 128 + lane * 4]);
            a4.x = fmaf(ww.x, vv.x, a4.x);
            a4.y = fmaf(ww.y, vv.y, a4.y);
            a4.z = fmaf(ww.z, vv.z, a4.z);
            a4.w = fmaf(ww.w, vv.w, a4.w);
        }
        float s = (a4.x + a4.y) + (a4.z + a4.w);
        #pragma unroll
        for (int o = 16; o; o >>= 1) s += __shfl_xor_sync(0xffffffffu, s, o);
        if (lane == 0) out[(size_t)b * DVn + vr0 + r] = s;
    }
}

} // namespace

extern "C" void kernel_launch(void* const* d_in, const int* in_sizes, int n_in,
                              void* d_out, int out_size)
{
    const float* Q    = (const float*)d_in[0];
    const float* K    = (const float*)d_in[1];
    const float* V    = (const float*)d_in[2];
    const int*   mask = (const int*)d_in[3];
    float*       out  = (float*)d_out;

    energy_kernel<<<Bn * 2, 256>>>(Q, K, mask);
    softmax_pv_kernel<<<Bn * 2, 256>>>(V, out);
}

// round 8
// speedup vs baseline: 1.0671x; 1.0671x over previous
#include <cuda_runtime.h>
#include <cuda_bf16.h>

namespace {

constexpr int Bn  = 512;
constexpr int DKn = 256;
constexpr int DVn = 256;
constexpr int Pn  = 2048;
constexpr float SCALEf = 1.0f / 16.0f;   // 1/sqrt(256)

// 128 threads/CTA, 4 CTAs/SM -> 592 slots >= 512 CTAs: single wave, no tail.
__global__ void __launch_bounds__(128, 4)
attn_kernel(const float* __restrict__ Q,
            const float* __restrict__ K,
            const float* __restrict__ V,
            const int*   __restrict__ mask,
            float*       __restrict__ out)
{
    __shared__ float sQ[DKn];
    __shared__ float sW[Pn];
    __shared__ float sRed[4];

    const int b    = blockIdx.x;
    const int t    = threadIdx.x;
    const int lane = t & 31;
    const int warp = t >> 5;

    // ---- Q row into smem ----
    sQ[t]       = Q[(size_t)b * DKn + t];
    sQ[t + 128] = Q[(size_t)b * DKn + t + 128];
    __syncthreads();

    // ---- Phase 1: energies. Thread owns 16 p-slots: 4 streams at 4t + j*512. ----
    const float* __restrict__ Kb = K + (size_t)b * DKn * Pn + 4 * t;

    float4 acc[4];
    #pragma unroll
    for (int j = 0; j < 4; ++j) acc[j] = make_float4(0.f, 0.f, 0.f, 0.f);

    // d-chunks of 4: 16 float4 loads issued before any FMA consumes them.
    #pragma unroll 1
    for (int d0 = 0; d0 < DKn; d0 += 4) {
        float4 kv[4][4];
        #pragma unroll
        for (int i = 0; i < 4; ++i) {
            const float* base = Kb + (size_t)(d0 + i) * Pn;
            #pragma unroll
            for (int j = 0; j < 4; ++j)
                kv[i][j] = *reinterpret_cast<const float4*>(base + j * 512);
        }
        #pragma unroll
        for (int i = 0; i < 4; ++i) {
            const float q = sQ[d0 + i];
            #pragma unroll
            for (int j = 0; j < 4; ++j) {
                acc[j].x = fmaf(q, kv[i][j].x, acc[j].x);
                acc[j].y = fmaf(q, kv[i][j].y, acc[j].y);
                acc[j].z = fmaf(q, kv[i][j].z, acc[j].z);
                acc[j].w = fmaf(q, kv[i][j].w, acc[j].w);
            }
        }
    }

    // ---- multiplicative mask + scale (masked -> exactly 0.0, NOT -inf) ----
    float e[16];
    #pragma unroll
    for (int j = 0; j < 4; ++j) {
        const int4 m = *reinterpret_cast<const int4*>(mask + (size_t)b * Pn + 4 * t + j * 512);
        e[4 * j + 0] = m.x ? acc[j].x * SCALEf : 0.f;
        e[4 * j + 1] = m.y ? acc[j].y * SCALEf : 0.f;
        e[4 * j + 2] = m.z ? acc[j].z * SCALEf : 0.f;
        e[4 * j + 3] = m.w ? acc[j].w * SCALEf : 0.f;
    }

    // ---- Phase 2: softmax over 2048 (4 warps) ----
    float lmax = e[0];
    #pragma unroll
    for (int i = 1; i < 16; ++i) lmax = fmaxf(lmax, e[i]);
    float v = lmax;
    #pragma unroll
    for (int o = 16; o; o >>= 1) v = fmaxf(v, __shfl_xor_sync(0xffffffffu, v, o));
    if (lane == 0) sRed[warp] = v;
    __syncthreads();
    const float gmax = fmaxf(fmaxf(sRed[0], sRed[1]), fmaxf(sRed[2], sRed[3]));
    __syncthreads();   // sRed reused for sum

    float w[16];
    float lsum = 0.f;
    #pragma unroll
    for (int i = 0; i < 16; ++i) {
        w[i] = __expf(e[i] - gmax);
        lsum += w[i];
    }
    #pragma unroll
    for (int j = 0; j < 4; ++j)
        *reinterpret_cast<float4*>(&sW[4 * t + j * 512]) =
            make_float4(w[4 * j + 0], w[4 * j + 1], w[4 * j + 2], w[4 * j + 3]);

    v = lsum;
    #pragma unroll
    for (int o = 16; o; o >>= 1) v += __shfl_xor_sync(0xffffffffu, v, o);
    if (lane == 0) sRed[warp] = v;
    __syncthreads();   // publishes sW + sums
    const float gsum = (sRed[0] + sRed[1]) + (sRed[2] + sRed[3]);
    const float inv = 1.0f / gsum;

    // ---- Phase 3: 4 warps x 64 output rows; 16 float4 in flight per row ----
    const float* __restrict__ Vb = V + (size_t)b * DVn * Pn;
    const int vr0 = warp * (DVn / 4);

    #pragma unroll 1
    for (int r = 0; r < DVn / 4; ++r) {
        const float* __restrict__ Vr = Vb + (size_t)(vr0 + r) * Pn + lane * 4;
        float4 a4 = make_float4(0.f, 0.f, 0.f, 0.f);
        #pragma unroll
        for (int i = 0; i < Pn / 128; ++i) {       // 16 iters
            const float4 vv = *reinterpret_cast<const float4*>(Vr + i * 128);
            const float4 ww = *reinterpret_cast<const float4*>(&sW[i * 128 + lane * 4]);
            a4.x = fmaf(ww.x, vv.x, a4.x);
            a4.y = fmaf(ww.y, vv.y, a4.y);
            a4.z = fmaf(ww.z, vv.z, a4.z);
            a4.w = fmaf(ww.w, vv.w, a4.w);
        }
        float s = (a4.x + a4.y) + (a4.z + a4.w);
        #pragma unroll
        for (int o = 16; o; o >>= 1) s += __shfl_xor_sync(0xffffffffu, s, o);
        if (lane == 0) out[(size_t)b * DVn + vr0 + r] = s * inv;
    }
}

} // namespace

extern "C" void kernel_launch(void* const* d_in, const int* in_sizes, int n_in,
                              void* d_out, int out_size)
{
    const float* Q    = (const float*)d_in[0];
    const float* K    = (const float*)d_in[1];
    const float* V    = (const float*)d_in[2];
    const int*   mask = (const int*)d_in[3];
    float*       out  = (float*)d_out;

    attn_kernel<<<Bn, 128>>>(Q, K, V, mask, out);
}

// round 9
// speedup vs baseline: 1.0851x; 1.0168x over previous
#include <cuda_runtime.h>
#include <cuda_bf16.h>

namespace {

constexpr int Bn  = 512;
constexpr int DKn = 256;
constexpr int DVn = 256;
constexpr int Pn  = 2048;
constexpr float SCALEf = 1.0f / 16.0f;   // 1/sqrt(256)

__global__ void __launch_bounds__(256, 2)
attn_kernel(const float* __restrict__ Q,
            const float* __restrict__ K,
            const float* __restrict__ V,
            const int*   __restrict__ mask,
            float*       __restrict__ out)
{
    __shared__ float sQ[DKn];
    __shared__ float sW[Pn];
    __shared__ float sRed[8];

    const int b    = blockIdx.x;
    const int t    = threadIdx.x;
    const int lane = t & 31;
    const int warp = t >> 5;

    // ---- Q row into smem ----
    sQ[t] = Q[(size_t)b * DKn + t];
    __syncthreads();

    const int pA = 4 * t;
    const int pB = (Pn / 2) + 4 * t;
    const float* __restrict__ KbA = K + (size_t)b * DKn * Pn + pA;
    const float* __restrict__ KbB = K + (size_t)b * DKn * Pn + pB;

    // prefetch mask early (hides the mask stream behind the K stream)
    const int4 mA = *reinterpret_cast<const int4*>(mask + (size_t)b * Pn + pA);
    const int4 mB = *reinterpret_cast<const int4*>(mask + (size_t)b * Pn + pB);

    // ---- Phase 1: depth-2 software-pipelined K stream ----
    // chunk = 4 d-rows x 2 streams = 8 float4 loads; two buffers alternate.
    float4 bufA[8], bufB[8];
    float4 aA = make_float4(0.f, 0.f, 0.f, 0.f);
    float4 aB = make_float4(0.f, 0.f, 0.f, 0.f);

#define LOAD_CHUNK(BUF, D0)                                                        \
    {                                                                              \
        _Pragma("unroll")                                                          \
        for (int i = 0; i < 4; ++i) {                                              \
            BUF[2*i]   = *reinterpret_cast<const float4*>(KbA + (size_t)((D0)+i) * Pn); \
            BUF[2*i+1] = *reinterpret_cast<const float4*>(KbB + (size_t)((D0)+i) * Pn); \
        }                                                                          \
    }
#define FMA_CHUNK(BUF, D0)                                                         \
    {                                                                              \
        _Pragma("unroll")                                                          \
        for (int i = 0; i < 4; ++i) {                                              \
            const float q = sQ[(D0)+i];                                            \
            aA.x = fmaf(q, BUF[2*i].x,   aA.x);                                    \
            aA.y = fmaf(q, BUF[2*i].y,   aA.y);                                    \
            aA.z = fmaf(q, BUF[2*i].z,   aA.z);                                    \
            aA.w = fmaf(q, BUF[2*i].w,   aA.w);                                    \
            aB.x = fmaf(q, BUF[2*i+1].x, aB.x);                                    \
            aB.y = fmaf(q, BUF[2*i+1].y, aB.y);                                    \
            aB.z = fmaf(q, BUF[2*i+1].z, aB.z);                                    \
            aB.w = fmaf(q, BUF[2*i+1].w, aB.w);                                    \
        }                                                                          \
    }

    LOAD_CHUNK(bufA, 0)
    #pragma unroll 1
    for (int d0 = 0; d0 < DKn; d0 += 8) {
        LOAD_CHUNK(bufB, d0 + 4)
        FMA_CHUNK(bufA, d0)
        if (d0 + 8 < DKn) LOAD_CHUNK(bufA, d0 + 8)
        FMA_CHUNK(bufB, d0 + 4)
    }
#undef LOAD_CHUNK
#undef FMA_CHUNK

    // ---- multiplicative mask + scale (masked -> exactly 0.0, NOT -inf) ----
    float e[8];
    e[0] = mA.x ? aA.x * SCALEf : 0.f;
    e[1] = mA.y ? aA.y * SCALEf : 0.f;
    e[2] = mA.z ? aA.z * SCALEf : 0.f;
    e[3] = mA.w ? aA.w * SCALEf : 0.f;
    e[4] = mB.x ? aB.x * SCALEf : 0.f;
    e[5] = mB.y ? aB.y * SCALEf : 0.f;
    e[6] = mB.z ? aB.z * SCALEf : 0.f;
    e[7] = mB.w ? aB.w * SCALEf : 0.f;

    // ---- Phase 2: softmax over 2048 ----
    float lmax = e[0];
    #pragma unroll
    for (int i = 1; i < 8; ++i) lmax = fmaxf(lmax, e[i]);
    float v = lmax;
    #pragma unroll
    for (int o = 16; o; o >>= 1) v = fmaxf(v, __shfl_xor_sync(0xffffffffu, v, o));
    if (lane == 0) sRed[warp] = v;
    __syncthreads();
    float gmax = sRed[0];
    #pragma unroll
    for (int i = 1; i < 8; ++i) gmax = fmaxf(gmax, sRed[i]);
    __syncthreads();   // sRed reused for sum

    float w[8];
    float lsum = 0.f;
    #pragma unroll
    for (int i = 0; i < 8; ++i) {
        w[i] = __expf(e[i] - gmax);
        lsum += w[i];
    }
    *reinterpret_cast<float4*>(&sW[pA]) = make_float4(w[0], w[1], w[2], w[3]);
    *reinterpret_cast<float4*>(&sW[pB]) = make_float4(w[4], w[5], w[6], w[7]);

    v = lsum;
    #pragma unroll
    for (int o = 16; o; o >>= 1) v += __shfl_xor_sync(0xffffffffu, v, o);
    if (lane == 0) sRed[warp] = v;
    __syncthreads();   // publishes sW + sums
    float gsum = sRed[0];
    #pragma unroll
    for (int i = 1; i < 8; ++i) gsum += sRed[i];
    const float inv = 1.0f / gsum;

    // ---- Phase 3: 8 warps x 32 rows, groups of 4 rows with deferred reduces ----
    const float* __restrict__ Vb = V + (size_t)b * DVn * Pn;
    const int rbase = warp * (DVn / 8);

    #pragma unroll 1
    for (int g = 0; g < DVn / 8; g += 4) {
        float s[4];
        #pragma unroll
        for (int r = 0; r < 4; ++r) {
            const float* __restrict__ Vr = Vb + (size_t)(rbase + g + r) * Pn + lane * 4;
            float4 a4 = make_float4(0.f, 0.f, 0.f, 0.f);
            #pragma unroll
            for (int i = 0; i < Pn / 128; ++i) {   // 16 float4 loads per row
                const float4 vv = *reinterpret_cast<const float4*>(Vr + i * 128);
                const float4 ww = *reinterpret_cast<const float4*>(&sW[i * 128 + lane * 4]);
                a4.x = fmaf(ww.x, vv.x, a4.x);
                a4.y = fmaf(ww.y, vv.y, a4.y);
                a4.z = fmaf(ww.z, vv.z, a4.z);
                a4.w = fmaf(ww.w, vv.w, a4.w);
            }
            s[r] = (a4.x + a4.y) + (a4.z + a4.w);
        }
        // 4 independent shfl chains, interleaved
        #pragma unroll
        for (int o = 16; o; o >>= 1) {
            s[0] += __shfl_xor_sync(0xffffffffu, s[0], o);
            s[1] += __shfl_xor_sync(0xffffffffu, s[1], o);
            s[2] += __shfl_xor_sync(0xffffffffu, s[2], o);
            s[3] += __shfl_xor_sync(0xffffffffu, s[3], o);
        }
        if (lane == 0) {
            float* op = out + (size_t)b * DVn + rbase + g;
            op[0] = s[0] * inv;
            op[1] = s[1] * inv;
            op[2] = s[2] * inv;
            op[3] = s[3] * inv;
        }
    }
}

} // namespace

extern "C" void kernel_launch(void* const* d_in, const int* in_sizes, int n_in,
                              void* d_out, int out_size)
{
    const float* Q    = (const float*)d_in[0];
    const float* K    = (const float*)d_in[1];
    const float* V    = (const float*)d_in[2];
    const int*   mask = (const int*)d_in[3];
    float*       out  = (float*)d_out;

    attn_kernel<<<Bn, 256>>>(Q, K, V, mask, out);
}